// round 13
// baseline (speedup 1.0000x reference)
#include <cuda_runtime.h>
#include <cuda_fp16.h>
#include <math.h>

// ---------------- problem constants ----------------
constexpr int NB = 256;    // batch
constexpr int NA = 285;    // angles
constexpr int ND = 183;    // detectors
constexpr int NI = 128;    // image N
constexpr int QQ = 184;    // quads per row (stride)

constexpr double RHO_D    = 1.4142135623730951 * 20.0;
constexpr double DC_D     = 2.0 * RHO_D / 183.0;
constexpr double INVDC_D  = 1.0 / DC_D;
constexpr double H0_D     = 1.0 / (4.0 * DC_D * DC_D);
constexpr double SCALEQ_D = 12.0 * DC_D;
constexpr double PI_D     = 3.141592653589793;

// filtered sinogram, fp16 4-image-interleaved (g0, delta) quads:
// Q[group][a][k] = halfs (g_b0[k],g_b1[k],g_b2[k],g_b3[k],
//                         (g[k+1]-g[k])_b0, ..., _b3)          (16B)
__device__ uint4 g_q[(size_t)(NB / 4) * NA * QQ];

// ================= Stage 1: ramp filter (banded conv) =================
// Block: 4 images (group) x 4 angles = 16 rows; 192 threads.
// Thread map: r = t&15 (row), l = t>>4 (output group of 16).
// -> warp = 16 rows x 2 l: G-window loads broadcast (2 addrs/warp),
//    x-row loads conflict-free with stride 204 (816B = 48 mod 128).
constexpr int XSTR = 204;

__global__ __launch_bounds__(192) void filter_kernel(const float* __restrict__ x,
                                                     uint4* __restrict__ Q) {
    __shared__ __align__(16) float xs[16 * XSTR];    // 16 rows, zero-padded
    __shared__ __align__(16) float Gs[224];          // Godd shifted +8, guarded
    __shared__ __align__(16) __half st[4 * 184 * 4]; // [va][n][im]

    const int t  = threadIdx.x;
    const int a0 = blockIdx.x * 4;                  // angle quad
    const int g  = blockIdx.y;                      // image group
    const int b0 = 4 * g;

    // Gs[j] = g(2*(j-8)-181) for j-8 in [0,181], else 0
    for (int jj = t; jj < 224; jj += 192) {
        int i = jj - 8;
        float v = 0.0f;
        if (i >= 0 && i <= 181) {
            int o = 2 * i - 181;                    // odd
            double d = PI_D * (double)o * DC_D;
            v = (float)(-1.0 / (d * d));
        }
        Gs[jj] = v;
    }

    // load 16 rows (row = va*4 + im), zero-padded to XSTR
    for (int u = t; u < 16 * XSTR; u += 192) {
        int row = u / XSTR, col = u - row * XSTR;
        int va = row >> 2, im = row & 3;
        int aa = a0 + va;
        float v = 0.0f;
        if (col < ND && aa < NA)
            v = x[((size_t)(b0 + im) * NA + aa) * ND + col];
        xs[u] = v;
    }
    __syncthreads();

    const int r  = t & 15;           // row 0..15
    const int l  = t >> 4;           // 0..11
    const int va = r >> 2, im = r & 3;
    const int n0 = 16 * l;
    const int E0 = 8 * l + 90;
    const float* xr = xs + r * XSTR;

    float acc[16];
    #pragma unroll
    for (int e = 0; e < 16; e++) acc[e] = 0.0f;

    // 23 unroll-4 blocks cover s = 0..91 (includes the even m=182 tap;
    // odd m=183 multiplies padded x[183]=0; Gs guard zeros absorb underrun)
    for (int s0 = 0; s0 < 92; s0 += 4) {
        float4 xq0 = *(const float4*)(xr + 2 * s0);      // x[2s0 .. 2s0+3]
        float4 xq1 = *(const float4*)(xr + 2 * s0 + 4);  // x[2s0+4 .. +7]
        const float4* Gv = (const float4*)(Gs + (E0 - s0 + 2)); // 4-aligned
        float4 g0v = Gv[0], g1v = Gv[1], g2v = Gv[2], g3v = Gv[3];
        float gg[16] = {g0v.x,g0v.y,g0v.z,g0v.w, g1v.x,g1v.y,g1v.z,g1v.w,
                        g2v.x,g2v.y,g2v.z,g2v.w, g3v.x,g3v.y,g3v.z,g3v.w};
        float xf[8] = {xq0.x,xq0.y,xq0.z,xq0.w, xq1.x,xq1.y,xq1.z,xq1.w};
        #pragma unroll
        for (int k = 0; k < 4; k++) {
            #pragma unroll
            for (int e = 0; e < 8; e++) {
                acc[2*e]   = fmaf(xf[2*k+1], gg[e + 6 - k], acc[2*e]);   // even n
                acc[2*e+1] = fmaf(xf[2*k],   gg[e + 7 - k], acc[2*e+1]); // odd n
            }
        }
    }
    { // center tap
        const float h0 = (float)H0_D;
        float4 c0 = *(const float4*)(xr + n0);
        float4 c1 = *(const float4*)(xr + n0 + 4);
        float4 c2 = *(const float4*)(xr + n0 + 8);
        float4 c3 = *(const float4*)(xr + n0 + 12);
        float cf[16] = {c0.x,c0.y,c0.z,c0.w, c1.x,c1.y,c1.z,c1.w,
                        c2.x,c2.y,c2.z,c2.w, c3.x,c3.y,c3.z,c3.w};
        #pragma unroll
        for (int e = 0; e < 16; e++) acc[e] = fmaf(h0, cf[e], acc[e]);
    }

    // stage as fp16: st[(va*184 + n)*4 + im]
    const float sc = (float)SCALEQ_D;
    #pragma unroll
    for (int e = 0; e < 16; e++) {
        int n = n0 + e;
        if (n < 184) st[(va * 184 + n) * 4 + im] = __float2half_rn(acc[e] * sc);
    }
    __syncthreads();

    // pack (g0, delta) quads
    for (int u = t; u < 4 * ND; u += 192) {
        int qa = u / ND, k = u - qa * ND;
        int aa = a0 + qa;
        if (aa < NA) {
            const uint2* sp = (const uint2*)(st + qa * 184 * 4);
            uint2 lo = sp[k];
            uint2 hi = sp[k + 1];
            __half2 dd0 = __hsub2(*(const __half2*)&hi.x, *(const __half2*)&lo.x);
            __half2 dd1 = __hsub2(*(const __half2*)&hi.y, *(const __half2*)&lo.y);
            Q[((size_t)g * NA + aa) * QQ + k] =
                make_uint4(lo.x, lo.y, *(const unsigned*)&dd0, *(const unsigned*)&dd1);
        }
    }
}

// ================= Stage 2: backprojection =================
// 8-row blocks, grid 512 = 16 seg x 32 bg -> SINGLE WAVE (512 <= 740
// resident), eff ~86.5% (3-vs-4 blocks/SM imbalance only). Fill traffic
// halves vs 4-row blocks. Static 3-buffer ring, stage-paired fp16
// accumulation (one HADD2 per 2 angles before f32 convert).
constexpr int APS    = 2;
constexpr int STAGES = (NA + APS - 1) / APS;   // 143
constexpr int CHUNK  = APS * 2 * QQ;           // 736
constexpr unsigned CHUNKB = CHUNK * 16;

__device__ __forceinline__ void cp_async16(unsigned dst, const void* src) {
    asm volatile("cp.async.cg.shared.global [%0], [%1], 16;" :: "r"(dst), "l"(src));
}

__global__ __launch_bounds__(256, 4) void backproj_kernel(const uint4* __restrict__ Q,
                                                          float* __restrict__ out) {
    __shared__ uint4  qb[3][CHUNK];    // 35328 B
    __shared__ float2 csn[NA];         //  2280 B -> 37.6 KB total

    const int t   = threadIdx.x;
    const int seg = blockIdx.x;        // 0..15 -> image rows [seg*8, seg*8+8)
    const int bg  = blockIdx.y;        // 0..31 -> images [bg*8, bg*8+8)

    for (int idx = t; idx < NA; idx += 256) {
        double th = ((double)idx + 0.5) * (PI_D / (double)NA);
        double s, c;
        sincos(th, &s, &c);
        csn[idx] = make_float2((float)(c * INVDC_D), (float)(s * INVDC_D));
    }

    const int j  = t & 127;
    const int i0 = seg * 8 + (t >> 7) * 4;
    const float Yj = -20.0f + ((float)j  + 0.5f) * 0.3125f;
    const float Xi = -20.0f + ((float)i0 + 0.5f) * 0.3125f;

    const uint4* Qb = Q + (size_t)(bg * 2) * NA * QQ;

    // hoisted 3-slot chunk decomposition over [0, 736)
    const int pp0 = t / 184,               c0i = t - pp0 * 184;
    const int u1  = t + 256;
    const int ai1 = (u1 >= 368) ? 1 : 0;
    const int v1  = u1 - ai1 * 368;
    const int pp1 = v1 / 184,              c1i = v1 - pp1 * 184;
    const int u2  = t + 512;
    const bool has2 = (u2 < CHUNK);
    const int v2  = u2 - 368;
    const int pp2 = has2 ? (v2 / 184) : 0, c2i = has2 ? (v2 - (v2 / 184) * 184) : 0;

    const uint4* src0 = Qb + ((size_t)pp0 * NA + 0  ) * QQ + c0i;
    const uint4* src1 = Qb + ((size_t)pp1 * NA + ai1) * QQ + c1i;
    const uint4* src2 = Qb + ((size_t)pp2 * NA + 1  ) * QQ + c2i;

    const unsigned sb = (unsigned)__cvta_generic_to_shared(&qb[0][0]);
    const unsigned d0 = sb + (unsigned)(((0  * 2 + pp0) * QQ + c0i) * 16);
    const unsigned d1 = sb + (unsigned)(((ai1 * 2 + pp1) * QQ + c1i) * 16);
    const unsigned d2 = sb + (unsigned)(((1  * 2 + pp2) * QQ + c2i) * 16);

    // prologue: prefetch stages 0..2 into buffers 0..2
    #pragma unroll
    for (int s = 0; s < 3; s++) {
        unsigned off = s * CHUNKB;
        cp_async16(d0 + off, src0);
        cp_async16(d1 + off, src1);
        if (has2) cp_async16(d2 + off, src2);
        asm volatile("cp.async.commit_group;");
        src0 += APS * QQ; src1 += APS * QQ; src2 += APS * QQ;
    }

    float acc[8][4];
    #pragma unroll
    for (int v = 0; v < 8; v++)
        #pragma unroll
        for (int ii = 0; ii < 4; ii++) acc[v][ii] = 0.0f;

    int cur = 0;
    for (int stg = 0; stg < STAGES; stg++) {
        asm volatile("cp.async.wait_group 2;");
        __syncthreads();

        const int a0 = 2 * stg;
        const uint4* qs = qb[cur];

        if (a0 + 1 < NA) {
            // ---- dual-angle stage (142 of 143) ----
            const float2 csA = csn[a0];
            const float2 csB = csn[a0 + 1];
            const float kfA = fmaf(csA.x, Xi, fmaf(csA.y, Yj, 91.0f));
            const float kfB = fmaf(csB.x, Xi, fmaf(csB.y, Yj, 91.0f));
            const float dkA = csA.x * 0.3125f;
            const float dkB = csB.x * 0.3125f;

            #pragma unroll
            for (int ii = 0; ii < 4; ii++) {
                float ka = fmaf((float)ii, dkA, kfA);
                float kb = fmaf((float)ii, dkB, kfB);
                int k0a = (int)ka;                  // in [0.2, 181.8]
                int k0b = (int)kb;
                float wa = ka - (float)k0a;
                float wb = kb - (float)k0b;
                __half2 w2a = __floats2half2_rn(wa, wa);
                __half2 w2b = __floats2half2_rn(wb, wb);
                #pragma unroll
                for (int gq = 0; gq < 2; gq++) {
                    uint4 qA = qs[gq * QQ + k0a];            // angle a0
                    uint4 qB = qs[2 * QQ + gq * QQ + k0b];   // angle a0+1
                    __half2 lo = __hadd2(
                        __hfma2(w2a, *(const __half2*)&qA.z, *(const __half2*)&qA.x),
                        __hfma2(w2b, *(const __half2*)&qB.z, *(const __half2*)&qB.x));
                    __half2 hi = __hadd2(
                        __hfma2(w2a, *(const __half2*)&qA.w, *(const __half2*)&qA.y),
                        __hfma2(w2b, *(const __half2*)&qB.w, *(const __half2*)&qB.y));
                    acc[gq * 4 + 0][ii] += __low2float(lo);
                    acc[gq * 4 + 1][ii] += __high2float(lo);
                    acc[gq * 4 + 2][ii] += __low2float(hi);
                    acc[gq * 4 + 3][ii] += __high2float(hi);
                }
            }
        } else {
            // ---- single-angle tail (stage 142: angle 284) ----
            const float2 csA = csn[a0];
            const float kfA = fmaf(csA.x, Xi, fmaf(csA.y, Yj, 91.0f));
            const float dkA = csA.x * 0.3125f;
            #pragma unroll
            for (int ii = 0; ii < 4; ii++) {
                float ka = fmaf((float)ii, dkA, kfA);
                int k0a = (int)ka;
                float wa = ka - (float)k0a;
                __half2 w2a = __floats2half2_rn(wa, wa);
                #pragma unroll
                for (int gq = 0; gq < 2; gq++) {
                    uint4 qA = qs[gq * QQ + k0a];
                    __half2 lo = __hfma2(w2a, *(const __half2*)&qA.z,
                                         *(const __half2*)&qA.x);
                    __half2 hi = __hfma2(w2a, *(const __half2*)&qA.w,
                                         *(const __half2*)&qA.y);
                    acc[gq * 4 + 0][ii] += __low2float(lo);
                    acc[gq * 4 + 1][ii] += __high2float(lo);
                    acc[gq * 4 + 2][ii] += __low2float(hi);
                    acc[gq * 4 + 3][ii] += __high2float(hi);
                }
            }
        }

        __syncthreads();   // all warps done reading qb[cur]

        // prefetch stage stg+3 into the freed buffer; always commit
        const int stp = stg + 3;
        if (stp < STAGES) {
            const unsigned off = cur * CHUNKB;
            const bool full = (2 * stp + 1 < NA);
            cp_async16(d0 + off, src0);
            if (full || ai1 == 0) cp_async16(d1 + off, src1);
            if (has2 && full)     cp_async16(d2 + off, src2);
            src0 += APS * QQ; src1 += APS * QQ; src2 += APS * QQ;
        }
        asm volatile("cp.async.commit_group;");

        cur = (cur == 2) ? 0 : cur + 1;
    }

    const float sc = (float)(PI_D / (double)NA);
    #pragma unroll
    for (int gq = 0; gq < 2; gq++) {
        #pragma unroll
        for (int rr = 0; rr < 4; rr++) {
            int img = bg * 8 + gq * 4 + rr;
            #pragma unroll
            for (int ii = 0; ii < 4; ii++) {
                out[(size_t)img * (NI * NI) + (size_t)(i0 + ii) * NI + j] =
                    acc[gq * 4 + rr][ii] * sc;
            }
        }
    }
}

// ================= launch =================
extern "C" void kernel_launch(void* const* d_in, const int* in_sizes, int n_in,
                              void* d_out, int out_size) {
    (void)in_sizes; (void)n_in; (void)out_size;
    const float* x = (const float*)d_in[0];
    float* out = (float*)d_out;

    uint4* qptr = nullptr;
    cudaGetSymbolAddress((void**)&qptr, g_q);

    filter_kernel<<<dim3((NA + 3) / 4, NB / 4), 192>>>(x, qptr);
    backproj_kernel<<<dim3(16, 32), 256>>>(qptr, out);
}

// round 14
// speedup vs baseline: 1.2954x; 1.2954x over previous
#include <cuda_runtime.h>
#include <cuda_fp16.h>
#include <math.h>

// ---------------- problem constants ----------------
constexpr int NB = 256;    // batch
constexpr int NA = 285;    // angles
constexpr int ND = 183;    // detectors
constexpr int NI = 128;    // image N
constexpr int QS = 183;    // quads per row (= ND, no pad)

constexpr double RHO_D    = 1.4142135623730951 * 20.0;
constexpr double DC_D     = 2.0 * RHO_D / 183.0;
constexpr double INVDC_D  = 1.0 / DC_D;
constexpr double H0_D     = 1.0 / (4.0 * DC_D * DC_D);
constexpr double SCALEQ_D = 12.0 * DC_D;
constexpr double PI_D     = 3.141592653589793;

// filtered sinogram, fp16 4-image-interleaved (g0, delta) quads:
// Q[group][a][k] = halfs (g_b0[k],..,g_b3[k], (g[k+1]-g[k])_b0,..,_b3)  (16B)
__device__ uint4 g_q[(size_t)(NB / 4) * NA * QS];

// ================= Stage 1: ramp filter (banded conv) =================
// (unchanged numerics; only the output row stride is now 183)
constexpr int XSTR = 204;

__global__ __launch_bounds__(192) void filter_kernel(const float* __restrict__ x,
                                                     uint4* __restrict__ Q) {
    __shared__ __align__(16) float xs[16 * XSTR];    // 16 rows, zero-padded
    __shared__ __align__(16) float Gs[224];          // Godd shifted +8, guarded
    __shared__ __align__(16) __half st[4 * 184 * 4]; // [va][n][im]

    const int t  = threadIdx.x;
    const int a0 = blockIdx.x * 4;                  // angle quad
    const int g  = blockIdx.y;                      // image group
    const int b0 = 4 * g;

    for (int jj = t; jj < 224; jj += 192) {
        int i = jj - 8;
        float v = 0.0f;
        if (i >= 0 && i <= 181) {
            int o = 2 * i - 181;                    // odd
            double d = PI_D * (double)o * DC_D;
            v = (float)(-1.0 / (d * d));
        }
        Gs[jj] = v;
    }

    for (int u = t; u < 16 * XSTR; u += 192) {
        int row = u / XSTR, col = u - row * XSTR;
        int va = row >> 2, im = row & 3;
        int aa = a0 + va;
        float v = 0.0f;
        if (col < ND && aa < NA)
            v = x[((size_t)(b0 + im) * NA + aa) * ND + col];
        xs[u] = v;
    }
    __syncthreads();

    const int r  = t & 15;           // row 0..15
    const int l  = t >> 4;           // 0..11
    const int va = r >> 2, im = r & 3;
    const int n0 = 16 * l;
    const int E0 = 8 * l + 90;
    const float* xr = xs + r * XSTR;

    float acc[16];
    #pragma unroll
    for (int e = 0; e < 16; e++) acc[e] = 0.0f;

    for (int s0 = 0; s0 < 92; s0 += 4) {
        float4 xq0 = *(const float4*)(xr + 2 * s0);
        float4 xq1 = *(const float4*)(xr + 2 * s0 + 4);
        const float4* Gv = (const float4*)(Gs + (E0 - s0 + 2));
        float4 g0v = Gv[0], g1v = Gv[1], g2v = Gv[2], g3v = Gv[3];
        float gg[16] = {g0v.x,g0v.y,g0v.z,g0v.w, g1v.x,g1v.y,g1v.z,g1v.w,
                        g2v.x,g2v.y,g2v.z,g2v.w, g3v.x,g3v.y,g3v.z,g3v.w};
        float xf[8] = {xq0.x,xq0.y,xq0.z,xq0.w, xq1.x,xq1.y,xq1.z,xq1.w};
        #pragma unroll
        for (int k = 0; k < 4; k++) {
            #pragma unroll
            for (int e = 0; e < 8; e++) {
                acc[2*e]   = fmaf(xf[2*k+1], gg[e + 6 - k], acc[2*e]);
                acc[2*e+1] = fmaf(xf[2*k],   gg[e + 7 - k], acc[2*e+1]);
            }
        }
    }
    {
        const float h0 = (float)H0_D;
        float4 c0 = *(const float4*)(xr + n0);
        float4 c1 = *(const float4*)(xr + n0 + 4);
        float4 c2 = *(const float4*)(xr + n0 + 8);
        float4 c3 = *(const float4*)(xr + n0 + 12);
        float cf[16] = {c0.x,c0.y,c0.z,c0.w, c1.x,c1.y,c1.z,c1.w,
                        c2.x,c2.y,c2.z,c2.w, c3.x,c3.y,c3.z,c3.w};
        #pragma unroll
        for (int e = 0; e < 16; e++) acc[e] = fmaf(h0, cf[e], acc[e]);
    }

    const float sc = (float)SCALEQ_D;
    #pragma unroll
    for (int e = 0; e < 16; e++) {
        int n = n0 + e;
        if (n < 184) st[(va * 184 + n) * 4 + im] = __float2half_rn(acc[e] * sc);
    }
    __syncthreads();

    // pack (g0, delta) quads; global row stride = 183
    for (int u = t; u < 4 * ND; u += 192) {
        int qa = u / ND, k = u - qa * ND;
        int aa = a0 + qa;
        if (aa < NA) {
            const uint2* sp = (const uint2*)(st + qa * 184 * 4);
            uint2 lo = sp[k];
            uint2 hi = sp[k + 1];
            __half2 dd0 = __hsub2(*(const __half2*)&hi.x, *(const __half2*)&lo.x);
            __half2 dd1 = __hsub2(*(const __half2*)&hi.y, *(const __half2*)&lo.y);
            Q[((size_t)g * NA + aa) * QS + k] =
                make_uint4(lo.x, lo.y, *(const unsigned*)&dd0, *(const unsigned*)&dd1);
        }
    }
}

// ================= Stage 2: backprojection =================
// R11 residency (4-row blocks, grid 1024, 5 blocks/SM) with:
//  * APS=3: 285 = 3*95 stages exactly, no tail branch
//  * 2-buffer ring, ONE barrier per stage (prefetch after barrier into the
//    buffer of stage s-1, which everyone finished before this barrier)
//  * triple fp16 pairing: 3 lerps chained with HADD2, one f32 flush / 3 angles
constexpr int APS3 = 3;
constexpr int NSTG = NA / APS3;          // 95
constexpr int CH   = APS3 * 2 * QS;      // 1098 quads / stage buffer
constexpr unsigned CHB = CH * 16;        // 17568 B

__device__ __forceinline__ void cp_async16(unsigned dst, const void* src) {
    asm volatile("cp.async.cg.shared.global [%0], [%1], 16;" :: "r"(dst), "l"(src));
}

__global__ __launch_bounds__(256, 5) void backproj_kernel(const uint4* __restrict__ Q,
                                                          float* __restrict__ out) {
    __shared__ uint4  qb[2][CH];       // 35136 B
    __shared__ float2 csn[NA];         //  2280 B -> 37.4 KB total

    const int t   = threadIdx.x;
    const int seg = blockIdx.x;        // 0..31 -> image rows [seg*4, seg*4+4)
    const int bg  = blockIdx.y;        // 0..31 -> images [bg*8, bg*8+8)

    for (int idx = t; idx < NA; idx += 256) {
        double th = ((double)idx + 0.5) * (PI_D / (double)NA);
        double s, c;
        sincos(th, &s, &c);
        csn[idx] = make_float2((float)(c * INVDC_D), (float)(s * INVDC_D));
    }

    const int j  = t & 127;
    const int i0 = seg * 4 + (t >> 7) * 2;
    const float Yj = -20.0f + ((float)j  + 0.5f) * 0.3125f;
    const float Xi = -20.0f + ((float)i0 + 0.5f) * 0.3125f;

    const uint4* Qb = Q + (size_t)(bg * 2) * NA * QS;

    // prefetch slots: linear chunk id u = t + 256*s over [0, 1098);
    // smem offset is just u*16, global offset precomputed per slot.
    int goff[5];
    #pragma unroll
    for (int s = 0; s < 5; s++) {
        int u = t + 256 * s;
        if (u < CH) {
            int ai = u / (2 * QS);
            int rr = u - ai * (2 * QS);
            int gq = rr / QS;
            int k  = rr - gq * QS;
            goff[s] = (gq * NA + ai) * QS + k;
        } else {
            goff[s] = 0;
        }
    }
    const bool v4 = (t + 1024 < CH);    // t < 74

    const unsigned sb0 = (unsigned)__cvta_generic_to_shared(&qb[0][0]);

    // prologue: stage 0 -> buffer 0
    #pragma unroll
    for (int s = 0; s < 4; s++)
        cp_async16(sb0 + (unsigned)(t + 256 * s) * 16, Qb + goff[s]);
    if (v4) cp_async16(sb0 + (unsigned)(t + 1024) * 16, Qb + goff[4]);
    asm volatile("cp.async.commit_group;");

    const uint4* Qnext = Qb + APS3 * QS;   // stage 1 source base

    float acc[8][2];
    #pragma unroll
    for (int v = 0; v < 8; v++) { acc[v][0] = 0.0f; acc[v][1] = 0.0f; }

    int cur = 0;
    for (int stg = 0; stg < NSTG; stg++) {
        asm volatile("cp.async.wait_group 0;");
        __syncthreads();   // buffer cur filled; everyone past stage stg-1

        // prefetch stage stg+1 into the other buffer (stage stg-1's, all read)
        if (stg + 1 < NSTG) {
            const unsigned bn = sb0 + (cur ^ 1) * CHB;
            #pragma unroll
            for (int s = 0; s < 4; s++)
                cp_async16(bn + (unsigned)(t + 256 * s) * 16, Qnext + goff[s]);
            if (v4) cp_async16(bn + (unsigned)(t + 1024) * 16, Qnext + goff[4]);
            Qnext += APS3 * QS;
        }
        asm volatile("cp.async.commit_group;");

        const int a0 = 3 * stg;
        const uint4* qs = qb[cur];

        const float2 cA = csn[a0];
        const float2 cB = csn[a0 + 1];
        const float2 cC = csn[a0 + 2];
        const float kfA = fmaf(cA.x, Xi, fmaf(cA.y, Yj, 91.0f));
        const float kfB = fmaf(cB.x, Xi, fmaf(cB.y, Yj, 91.0f));
        const float kfC = fmaf(cC.x, Xi, fmaf(cC.y, Yj, 91.0f));
        const float dkA = cA.x * 0.3125f;
        const float dkB = cB.x * 0.3125f;
        const float dkC = cC.x * 0.3125f;

        #pragma unroll
        for (int ii = 0; ii < 2; ii++) {
            float ka = fmaf((float)ii, dkA, kfA);
            float kb = fmaf((float)ii, dkB, kfB);
            float kc = fmaf((float)ii, dkC, kfC);
            int k0a = (int)ka;                  // kf in [0.2, 181.8]
            int k0b = (int)kb;
            int k0c = (int)kc;
            float wa = ka - (float)k0a;
            float wb = kb - (float)k0b;
            float wc = kc - (float)k0c;
            __half2 w2a = __floats2half2_rn(wa, wa);
            __half2 w2b = __floats2half2_rn(wb, wb);
            __half2 w2c = __floats2half2_rn(wc, wc);
            #pragma unroll
            for (int gq = 0; gq < 2; gq++) {
                uint4 qA = qs[gq * QS + k0a];                // angle a0
                uint4 qB = qs[2 * QS + gq * QS + k0b];       // angle a0+1
                uint4 qC = qs[4 * QS + gq * QS + k0c];       // angle a0+2
                __half2 lo = __hadd2(__hadd2(
                    __hfma2(w2a, *(const __half2*)&qA.z, *(const __half2*)&qA.x),
                    __hfma2(w2b, *(const __half2*)&qB.z, *(const __half2*)&qB.x)),
                    __hfma2(w2c, *(const __half2*)&qC.z, *(const __half2*)&qC.x));
                __half2 hi = __hadd2(__hadd2(
                    __hfma2(w2a, *(const __half2*)&qA.w, *(const __half2*)&qA.y),
                    __hfma2(w2b, *(const __half2*)&qB.w, *(const __half2*)&qB.y)),
                    __hfma2(w2c, *(const __half2*)&qC.w, *(const __half2*)&qC.y));
                acc[gq * 4 + 0][ii] += __low2float(lo);
                acc[gq * 4 + 1][ii] += __high2float(lo);
                acc[gq * 4 + 2][ii] += __low2float(hi);
                acc[gq * 4 + 3][ii] += __high2float(hi);
            }
        }

        cur ^= 1;
    }

    const float sc = (float)(PI_D / (double)NA);
    #pragma unroll
    for (int gq = 0; gq < 2; gq++) {
        #pragma unroll
        for (int rr = 0; rr < 4; rr++) {
            int img = bg * 8 + gq * 4 + rr;
            #pragma unroll
            for (int ii = 0; ii < 2; ii++) {
                out[(size_t)img * (NI * NI) + (size_t)(i0 + ii) * NI + j] =
                    acc[gq * 4 + rr][ii] * sc;
            }
        }
    }
}

// ================= launch =================
extern "C" void kernel_launch(void* const* d_in, const int* in_sizes, int n_in,
                              void* d_out, int out_size) {
    (void)in_sizes; (void)n_in; (void)out_size;
    const float* x = (const float*)d_in[0];
    float* out = (float*)d_out;

    uint4* qptr = nullptr;
    cudaGetSymbolAddress((void**)&qptr, g_q);

    filter_kernel<<<dim3((NA + 3) / 4, NB / 4), 192>>>(x, qptr);
    backproj_kernel<<<dim3(32, 32), 256>>>(qptr, out);
}

// round 15
// speedup vs baseline: 1.3250x; 1.0229x over previous
#include <cuda_runtime.h>
#include <cuda_fp16.h>
#include <math.h>

// ---------------- problem constants ----------------
constexpr int NB = 256;    // batch
constexpr int NA = 285;    // angles
constexpr int ND = 183;    // detectors
constexpr int NI = 128;    // image N
constexpr int QQ = 184;    // quads per row (stride)

constexpr double RHO_D    = 1.4142135623730951 * 20.0;
constexpr double DC_D     = 2.0 * RHO_D / 183.0;
constexpr double INVDC_D  = 1.0 / DC_D;
constexpr double H0_D     = 1.0 / (4.0 * DC_D * DC_D);
constexpr double SCALEQ_D = 12.0 * DC_D;
constexpr double PI_D     = 3.141592653589793;
constexpr float  DC_F     = (float)DC_D;

// filtered sinogram, fp16 4-image-interleaved (g0, delta) quads:
// Q[group][a][k] = halfs (g_b0[k],..,g_b3[k], (g[k+1]-g[k])_b0,..,_b3) (16B)
__device__ uint4 g_q[(size_t)(NB / 4) * NA * QQ];

// ================= Stage 1: ramp filter (banded conv) =================
// Block: 4 images (group) x 4 angles = 16 rows; 192 threads.
// Thread map: r = t&15 (row), l = t>>4 (output group of 16).
constexpr int XSTR = 204;

__global__ __launch_bounds__(192) void filter_kernel(const float* __restrict__ x,
                                                     uint4* __restrict__ Q) {
    __shared__ __align__(16) float xs[16 * XSTR];    // 16 rows, zero-padded
    __shared__ __align__(16) float Gs[224];          // Godd shifted +8, guarded
    __shared__ __align__(16) __half st[4 * 184 * 4]; // [va][n][im]

    const int t  = threadIdx.x;
    const int a0 = blockIdx.x * 4;                  // angle quad
    const int g  = blockIdx.y;                      // image group
    const int b0 = 4 * g;

    // Gs[j] = g(2*(j-8)-181) for j-8 in [0,181], else 0   (fp32 math)
    for (int jj = t; jj < 224; jj += 192) {
        int i = jj - 8;
        float v = 0.0f;
        if (i >= 0 && i <= 181) {
            int o = 2 * i - 181;                    // odd
            float d = 3.14159265358979f * (float)o * DC_F;
            v = -1.0f / (d * d);
        }
        Gs[jj] = v;
    }

    // load 16 rows (row = va*4 + im), zero-padded to XSTR
    for (int u = t; u < 16 * XSTR; u += 192) {
        int row = u / XSTR, col = u - row * XSTR;
        int va = row >> 2, im = row & 3;
        int aa = a0 + va;
        float v = 0.0f;
        if (col < ND && aa < NA)
            v = x[((size_t)(b0 + im) * NA + aa) * ND + col];
        xs[u] = v;
    }
    __syncthreads();

    const int r  = t & 15;           // row 0..15
    const int l  = t >> 4;           // 0..11
    const int va = r >> 2, im = r & 3;
    const int n0 = 16 * l;
    const int E0 = 8 * l + 90;
    const float* xr = xs + r * XSTR;

    float acc[16];
    #pragma unroll
    for (int e = 0; e < 16; e++) acc[e] = 0.0f;

    // 23 unroll-4 blocks cover s = 0..91 (even m=182 tap included;
    // odd m=183 hits padded zero; Gs guard zeros absorb underrun)
    for (int s0 = 0; s0 < 92; s0 += 4) {
        float4 xq0 = *(const float4*)(xr + 2 * s0);
        float4 xq1 = *(const float4*)(xr + 2 * s0 + 4);
        const float4* Gv = (const float4*)(Gs + (E0 - s0 + 2));
        float4 g0v = Gv[0], g1v = Gv[1], g2v = Gv[2], g3v = Gv[3];
        float gg[16] = {g0v.x,g0v.y,g0v.z,g0v.w, g1v.x,g1v.y,g1v.z,g1v.w,
                        g2v.x,g2v.y,g2v.z,g2v.w, g3v.x,g3v.y,g3v.z,g3v.w};
        float xf[8] = {xq0.x,xq0.y,xq0.z,xq0.w, xq1.x,xq1.y,xq1.z,xq1.w};
        #pragma unroll
        for (int k = 0; k < 4; k++) {
            #pragma unroll
            for (int e = 0; e < 8; e++) {
                acc[2*e]   = fmaf(xf[2*k+1], gg[e + 6 - k], acc[2*e]);   // even n
                acc[2*e+1] = fmaf(xf[2*k],   gg[e + 7 - k], acc[2*e+1]); // odd n
            }
        }
    }
    { // center tap
        const float h0 = (float)H0_D;
        float4 c0 = *(const float4*)(xr + n0);
        float4 c1 = *(const float4*)(xr + n0 + 4);
        float4 c2 = *(const float4*)(xr + n0 + 8);
        float4 c3 = *(const float4*)(xr + n0 + 12);
        float cf[16] = {c0.x,c0.y,c0.z,c0.w, c1.x,c1.y,c1.z,c1.w,
                        c2.x,c2.y,c2.z,c2.w, c3.x,c3.y,c3.z,c3.w};
        #pragma unroll
        for (int e = 0; e < 16; e++) acc[e] = fmaf(h0, cf[e], acc[e]);
    }

    // stage as fp16: st[(va*184 + n)*4 + im]
    const float sc = (float)SCALEQ_D;
    #pragma unroll
    for (int e = 0; e < 16; e++) {
        int n = n0 + e;
        if (n < 184) st[(va * 184 + n) * 4 + im] = __float2half_rn(acc[e] * sc);
    }
    __syncthreads();

    // pack (g0, delta) quads
    for (int u = t; u < 4 * ND; u += 192) {
        int qa = u / ND, k = u - qa * ND;
        int aa = a0 + qa;
        if (aa < NA) {
            const uint2* sp = (const uint2*)(st + qa * 184 * 4);
            uint2 lo = sp[k];
            uint2 hi = sp[k + 1];
            __half2 dd0 = __hsub2(*(const __half2*)&hi.x, *(const __half2*)&lo.x);
            __half2 dd1 = __hsub2(*(const __half2*)&hi.y, *(const __half2*)&lo.y);
            Q[((size_t)g * NA + aa) * QQ + k] =
                make_uint4(lo.x, lo.y, *(const unsigned*)&dd0, *(const unsigned*)&dd1);
        }
    }
}

// ================= Stage 2: backprojection =================
// R11 config: 4-row blocks (grid 1024), static 3-buffer ring, APS=2,
// wait_group 2 (2-stage lookahead), stage-paired fp16 accumulation.
constexpr int APS    = 2;
constexpr int STAGES = (NA + APS - 1) / APS;   // 143
constexpr int CHUNK  = APS * 2 * QQ;           // 736
constexpr unsigned CHUNKB = CHUNK * 16;

__device__ __forceinline__ void cp_async16(unsigned dst, const void* src) {
    asm volatile("cp.async.cg.shared.global [%0], [%1], 16;" :: "r"(dst), "l"(src));
}

__global__ __launch_bounds__(256, 5) void backproj_kernel(const uint4* __restrict__ Q,
                                                          float* __restrict__ out) {
    __shared__ uint4  qb[3][CHUNK];    // 35328 B
    __shared__ float2 csn[NA];         //  2280 B -> 37.6 KB total

    const int t   = threadIdx.x;
    const int seg = blockIdx.x;        // 0..31 -> image rows [seg*4, seg*4+4)
    const int bg  = blockIdx.y;        // 0..31 -> images [bg*8, bg*8+8)

    // fp32 trig: err ~1e-7 -> kf err ~1e-5, negligible vs fp16 storage noise
    for (int idx = t; idx < NA; idx += 256) {
        float th = ((float)idx + 0.5f) * (float)(PI_D / (double)NA);
        float s, c;
        sincosf(th, &s, &c);
        csn[idx] = make_float2(c * (float)INVDC_D, s * (float)INVDC_D);
    }

    const int j  = t & 127;
    const int i0 = seg * 4 + (t >> 7) * 2;
    const float Yj = -20.0f + ((float)j  + 0.5f) * 0.3125f;
    const float Xi = -20.0f + ((float)i0 + 0.5f) * 0.3125f;

    const uint4* Qb = Q + (size_t)(bg * 2) * NA * QQ;

    // hoisted 3-slot chunk decomposition over [0, 736)
    const int pp0 = t / 184,               c0i = t - pp0 * 184;
    const int u1  = t + 256;
    const int ai1 = (u1 >= 368) ? 1 : 0;
    const int v1  = u1 - ai1 * 368;
    const int pp1 = v1 / 184,              c1i = v1 - pp1 * 184;
    const int u2  = t + 512;
    const bool has2 = (u2 < CHUNK);
    const int v2  = u2 - 368;
    const int pp2 = has2 ? (v2 / 184) : 0, c2i = has2 ? (v2 - (v2 / 184) * 184) : 0;

    const uint4* src0 = Qb + ((size_t)pp0 * NA + 0  ) * QQ + c0i;
    const uint4* src1 = Qb + ((size_t)pp1 * NA + ai1) * QQ + c1i;
    const uint4* src2 = Qb + ((size_t)pp2 * NA + 1  ) * QQ + c2i;

    const unsigned sb = (unsigned)__cvta_generic_to_shared(&qb[0][0]);
    const unsigned d0 = sb + (unsigned)(((0  * 2 + pp0) * QQ + c0i) * 16);
    const unsigned d1 = sb + (unsigned)(((ai1 * 2 + pp1) * QQ + c1i) * 16);
    const unsigned d2 = sb + (unsigned)(((1  * 2 + pp2) * QQ + c2i) * 16);

    // prologue: prefetch stages 0..2 into buffers 0..2
    #pragma unroll
    for (int s = 0; s < 3; s++) {
        unsigned off = s * CHUNKB;
        cp_async16(d0 + off, src0);
        cp_async16(d1 + off, src1);
        if (has2) cp_async16(d2 + off, src2);
        asm volatile("cp.async.commit_group;");
        src0 += APS * QQ; src1 += APS * QQ; src2 += APS * QQ;
    }

    float acc[8][2];
    #pragma unroll
    for (int v = 0; v < 8; v++) { acc[v][0] = 0.0f; acc[v][1] = 0.0f; }

    int cur = 0;
    for (int stg = 0; stg < STAGES; stg++) {
        asm volatile("cp.async.wait_group 2;");
        __syncthreads();

        const int a0 = 2 * stg;
        const uint4* qs = qb[cur];

        if (a0 + 1 < NA) {
            // ---- dual-angle stage (142 of 143) ----
            const float2 csA = csn[a0];
            const float2 csB = csn[a0 + 1];
            const float kfA = fmaf(csA.x, Xi, fmaf(csA.y, Yj, 91.0f));
            const float kfB = fmaf(csB.x, Xi, fmaf(csB.y, Yj, 91.0f));
            const float dkA = csA.x * 0.3125f;
            const float dkB = csB.x * 0.3125f;

            #pragma unroll
            for (int ii = 0; ii < 2; ii++) {
                float ka = fmaf((float)ii, dkA, kfA);
                float kb = fmaf((float)ii, dkB, kfB);
                int k0a = (int)ka;                  // in [0.2, 181.8]
                int k0b = (int)kb;
                float wa = ka - (float)k0a;
                float wb = kb - (float)k0b;
                __half2 w2a = __floats2half2_rn(wa, wa);
                __half2 w2b = __floats2half2_rn(wb, wb);
                #pragma unroll
                for (int gq = 0; gq < 2; gq++) {
                    uint4 qA = qs[gq * QQ + k0a];            // angle a0
                    uint4 qB = qs[2 * QQ + gq * QQ + k0b];   // angle a0+1
                    __half2 lo = __hadd2(
                        __hfma2(w2a, *(const __half2*)&qA.z, *(const __half2*)&qA.x),
                        __hfma2(w2b, *(const __half2*)&qB.z, *(const __half2*)&qB.x));
                    __half2 hi = __hadd2(
                        __hfma2(w2a, *(const __half2*)&qA.w, *(const __half2*)&qA.y),
                        __hfma2(w2b, *(const __half2*)&qB.w, *(const __half2*)&qB.y));
                    acc[gq * 4 + 0][ii] += __low2float(lo);
                    acc[gq * 4 + 1][ii] += __high2float(lo);
                    acc[gq * 4 + 2][ii] += __low2float(hi);
                    acc[gq * 4 + 3][ii] += __high2float(hi);
                }
            }
        } else {
            // ---- single-angle tail (stage 142: angle 284) ----
            const float2 csA = csn[a0];
            const float kfA = fmaf(csA.x, Xi, fmaf(csA.y, Yj, 91.0f));
            const float dkA = csA.x * 0.3125f;
            #pragma unroll
            for (int ii = 0; ii < 2; ii++) {
                float ka = fmaf((float)ii, dkA, kfA);
                int k0a = (int)ka;
                float wa = ka - (float)k0a;
                __half2 w2a = __floats2half2_rn(wa, wa);
                #pragma unroll
                for (int gq = 0; gq < 2; gq++) {
                    uint4 qA = qs[gq * QQ + k0a];
                    __half2 lo = __hfma2(w2a, *(const __half2*)&qA.z,
                                         *(const __half2*)&qA.x);
                    __half2 hi = __hfma2(w2a, *(const __half2*)&qA.w,
                                         *(const __half2*)&qA.y);
                    acc[gq * 4 + 0][ii] += __low2float(lo);
                    acc[gq * 4 + 1][ii] += __high2float(lo);
                    acc[gq * 4 + 2][ii] += __low2float(hi);
                    acc[gq * 4 + 3][ii] += __high2float(hi);
                }
            }
        }

        __syncthreads();   // all warps done reading qb[cur]

        // prefetch stage stg+3 into the freed buffer; always commit
        const int stp = stg + 3;
        if (stp < STAGES) {
            const unsigned off = cur * CHUNKB;
            const bool full = (2 * stp + 1 < NA);
            cp_async16(d0 + off, src0);
            if (full || ai1 == 0) cp_async16(d1 + off, src1);
            if (has2 && full)     cp_async16(d2 + off, src2);
            src0 += APS * QQ; src1 += APS * QQ; src2 += APS * QQ;
        }
        asm volatile("cp.async.commit_group;");

        cur = (cur == 2) ? 0 : cur + 1;
    }

    const float sc = (float)(PI_D / (double)NA);
    #pragma unroll
    for (int gq = 0; gq < 2; gq++) {
        #pragma unroll
        for (int rr = 0; rr < 4; rr++) {
            int img = bg * 8 + gq * 4 + rr;
            #pragma unroll
            for (int ii = 0; ii < 2; ii++) {
                out[(size_t)img * (NI * NI) + (size_t)(i0 + ii) * NI + j] =
                    acc[gq * 4 + rr][ii] * sc;
            }
        }
    }
}

// ================= launch =================
extern "C" void kernel_launch(void* const* d_in, const int* in_sizes, int n_in,
                              void* d_out, int out_size) {
    (void)in_sizes; (void)n_in; (void)out_size;
    const float* x = (const float*)d_in[0];
    float* out = (float*)d_out;

    uint4* qptr = nullptr;
    cudaGetSymbolAddress((void**)&qptr, g_q);

    filter_kernel<<<dim3((NA + 3) / 4, NB / 4), 192>>>(x, qptr);
    backproj_kernel<<<dim3(32, 32), 256>>>(qptr, out);
}

// round 16
// speedup vs baseline: 1.3343x; 1.0070x over previous
#include <cuda_runtime.h>
#include <cuda_fp16.h>
#include <math.h>

// ---------------- problem constants ----------------
constexpr int NB = 256;    // batch
constexpr int NA = 285;    // angles
constexpr int ND = 183;    // detectors
constexpr int NI = 128;    // image N
constexpr int QQ = 184;    // quads per row (stride)

constexpr double RHO_D    = 1.4142135623730951 * 20.0;
constexpr double DC_D     = 2.0 * RHO_D / 183.0;
constexpr double INVDC_D  = 1.0 / DC_D;
constexpr double H0_D     = 1.0 / (4.0 * DC_D * DC_D);
constexpr double SCALEQ_D = 12.0 * DC_D;
constexpr double PI_D     = 3.141592653589793;
constexpr float  DC_F     = (float)DC_D;

// filtered sinogram, fp16 4-image-interleaved (g0, delta) quads:
// Q[group][a][k] = halfs (g_b0[k],..,g_b3[k], (g[k+1]-g[k])_b0,..,_b3) (16B)
__device__ uint4 g_q[(size_t)(NB / 4) * NA * QQ];

// ================= Stage 1: ramp filter via packed f32x2 FMA ============
// Per thread: 16 outputs. Accumulator pairs PA[e] = packed (lo=acc[2e+1],
// hi=acc[2e]). Per detector-pair s: multiplier = natural pair
// (x[2s], x[2s+1]) (one LDS.64); coefficient = (G[I+1], G[I]) served as one
// aligned LDS.64 from pair-swapped tables GS2/GT2. FMA sequence per output
// is identical to the scalar version -> bitwise-equal results.
constexpr int XSTR = 204;

__device__ __forceinline__ void ffma2(unsigned long long& acc,
                                      unsigned long long a,
                                      unsigned long long b) {
    asm("fma.rn.f32x2 %0, %1, %2, %0;" : "+l"(acc) : "l"(a), "l"(b));
}

__global__ __launch_bounds__(192) void filter_kernel(const float* __restrict__ x,
                                                     uint4* __restrict__ Q) {
    // xs rows: stride XSTR floats, rows >=8 offset +16 floats (bank de-conflict)
    __shared__ __align__(16) float  xs[16 * XSTR + 16];
    __shared__ __align__(16) float  Gs[224];          // Godd shifted +8, guarded
    __shared__ __align__(8)  float2 GS2[112];         // (Gs[2m+1], Gs[2m])
    __shared__ __align__(8)  float2 GT2[112];         // (Gs[2m+2], Gs[2m+1])
    __shared__ __align__(16) __half st[4 * 184 * 4];  // [va][n][im]

    const int t  = threadIdx.x;
    const int a0 = blockIdx.x * 4;                  // angle quad
    const int g  = blockIdx.y;                      // image group
    const int b0 = 4 * g;

    // Gs[j] = g(2*(j-8)-181) for j-8 in [0,181], else 0
    for (int jj = t; jj < 224; jj += 192) {
        int i = jj - 8;
        float v = 0.0f;
        if (i >= 0 && i <= 181) {
            int o = 2 * i - 181;                    // odd
            float d = 3.14159265358979f * (float)o * DC_F;
            v = -1.0f / (d * d);
        }
        Gs[jj] = v;
    }

    // load 16 rows (row = va*4 + im), zero-padded to XSTR, swizzled base
    for (int u = t; u < 16 * XSTR; u += 192) {
        int row = u / XSTR, col = u - row * XSTR;
        int va = row >> 2, im = row & 3;
        int aa = a0 + va;
        float v = 0.0f;
        if (col < ND && aa < NA)
            v = x[((size_t)(b0 + im) * NA + aa) * ND + col];
        xs[row * XSTR + ((row & 8) << 1) + col] = v;
    }
    __syncthreads();

    // pair-swapped coefficient tables
    for (int m = t; m < 112; m += 192) {
        float e0 = Gs[2 * m];
        float e1 = Gs[2 * m + 1];
        float e2 = (2 * m + 2 < 224) ? Gs[2 * m + 2] : 0.0f;
        GS2[m] = make_float2(e1, e0);
        GT2[m] = make_float2(e2, e1);
    }
    __syncthreads();

    const int r  = t & 15;           // row 0..15
    const int l  = t >> 4;           // 0..11
    const int va = r >> 2, im = r & 3;
    const int n0 = 16 * l;
    const int C0 = 4 * l + 49;       // (E0+8)/2, E0 = 8l+90
    const float* xr = xs + r * XSTR + ((r & 8) << 1);

    unsigned long long PA[8];
    #pragma unroll
    for (int e = 0; e < 8; e++) PA[e] = 0ULL;

    // 48 pairs cover s = 0..95 (s=92..95 multiply padded zeros -> exact 0)
    #pragma unroll 4
    for (int p = 0; p < 48; p++) {
        const int c = C0 - p;
        unsigned long long xa = *(const unsigned long long*)(xr + 4 * p);
        unsigned long long xb = *(const unsigned long long*)(xr + 4 * p + 2);
        const unsigned long long* gs = (const unsigned long long*)GS2 + c;
        const unsigned long long* gt = (const unsigned long long*)GT2 + c;
        // s_a = 2p (u even): e even -> GS2[c+e/2], e odd -> GT2[c+(e-1)/2]
        #pragma unroll
        for (int e = 0; e < 8; e++)
            ffma2(PA[e], xa, (e & 1) ? gt[e >> 1] : gs[e >> 1]);
        // s_b = 2p+1 (u odd): e odd -> GS2[c+(e-1)/2], e even -> GT2[c-1+e/2]
        #pragma unroll
        for (int e = 0; e < 8; e++)
            ffma2(PA[e], xb, (e & 1) ? gs[e >> 1] : gt[(e >> 1) - 1]);
    }

    // unpack: PA[e] = (lo = acc[2e+1], hi = acc[2e])
    float acc[16];
    #pragma unroll
    for (int e = 0; e < 8; e++) {
        float lo, hi;
        asm("mov.b64 {%0, %1}, %2;" : "=f"(lo), "=f"(hi) : "l"(PA[e]));
        acc[2 * e]     = hi;
        acc[2 * e + 1] = lo;
    }

    { // center tap
        const float h0 = (float)H0_D;
        float4 c0 = *(const float4*)(xr + n0);
        float4 c1 = *(const float4*)(xr + n0 + 4);
        float4 c2 = *(const float4*)(xr + n0 + 8);
        float4 c3 = *(const float4*)(xr + n0 + 12);
        float cf[16] = {c0.x,c0.y,c0.z,c0.w, c1.x,c1.y,c1.z,c1.w,
                        c2.x,c2.y,c2.z,c2.w, c3.x,c3.y,c3.z,c3.w};
        #pragma unroll
        for (int e = 0; e < 16; e++) acc[e] = fmaf(h0, cf[e], acc[e]);
    }

    // stage as fp16: st[(va*184 + n)*4 + im]
    const float sc = (float)SCALEQ_D;
    #pragma unroll
    for (int e = 0; e < 16; e++) {
        int n = n0 + e;
        if (n < 184) st[(va * 184 + n) * 4 + im] = __float2half_rn(acc[e] * sc);
    }
    __syncthreads();

    // pack (g0, delta) quads
    for (int u = t; u < 4 * ND; u += 192) {
        int qa = u / ND, k = u - qa * ND;
        int aa = a0 + qa;
        if (aa < NA) {
            const uint2* sp = (const uint2*)(st + qa * 184 * 4);
            uint2 lo = sp[k];
            uint2 hi = sp[k + 1];
            __half2 dd0 = __hsub2(*(const __half2*)&hi.x, *(const __half2*)&lo.x);
            __half2 dd1 = __hsub2(*(const __half2*)&hi.y, *(const __half2*)&lo.y);
            Q[((size_t)g * NA + aa) * QQ + k] =
                make_uint4(lo.x, lo.y, *(const unsigned*)&dd0, *(const unsigned*)&dd1);
        }
    }
}

// ================= Stage 2: backprojection (R15, unchanged) =============
constexpr int APS    = 2;
constexpr int STAGES = (NA + APS - 1) / APS;   // 143
constexpr int CHUNK  = APS * 2 * QQ;           // 736
constexpr unsigned CHUNKB = CHUNK * 16;

__device__ __forceinline__ void cp_async16(unsigned dst, const void* src) {
    asm volatile("cp.async.cg.shared.global [%0], [%1], 16;" :: "r"(dst), "l"(src));
}

__global__ __launch_bounds__(256, 5) void backproj_kernel(const uint4* __restrict__ Q,
                                                          float* __restrict__ out) {
    __shared__ uint4  qb[3][CHUNK];    // 35328 B
    __shared__ float2 csn[NA];         //  2280 B -> 37.6 KB total

    const int t   = threadIdx.x;
    const int seg = blockIdx.x;        // 0..31 -> image rows [seg*4, seg*4+4)
    const int bg  = blockIdx.y;        // 0..31 -> images [bg*8, bg*8+8)

    for (int idx = t; idx < NA; idx += 256) {
        float th = ((float)idx + 0.5f) * (float)(PI_D / (double)NA);
        float s, c;
        sincosf(th, &s, &c);
        csn[idx] = make_float2(c * (float)INVDC_D, s * (float)INVDC_D);
    }

    const int j  = t & 127;
    const int i0 = seg * 4 + (t >> 7) * 2;
    const float Yj = -20.0f + ((float)j  + 0.5f) * 0.3125f;
    const float Xi = -20.0f + ((float)i0 + 0.5f) * 0.3125f;

    const uint4* Qb = Q + (size_t)(bg * 2) * NA * QQ;

    // hoisted 3-slot chunk decomposition over [0, 736)
    const int pp0 = t / 184,               c0i = t - pp0 * 184;
    const int u1  = t + 256;
    const int ai1 = (u1 >= 368) ? 1 : 0;
    const int v1  = u1 - ai1 * 368;
    const int pp1 = v1 / 184,              c1i = v1 - pp1 * 184;
    const int u2  = t + 512;
    const bool has2 = (u2 < CHUNK);
    const int v2  = u2 - 368;
    const int pp2 = has2 ? (v2 / 184) : 0, c2i = has2 ? (v2 - (v2 / 184) * 184) : 0;

    const uint4* src0 = Qb + ((size_t)pp0 * NA + 0  ) * QQ + c0i;
    const uint4* src1 = Qb + ((size_t)pp1 * NA + ai1) * QQ + c1i;
    const uint4* src2 = Qb + ((size_t)pp2 * NA + 1  ) * QQ + c2i;

    const unsigned sb = (unsigned)__cvta_generic_to_shared(&qb[0][0]);
    const unsigned d0 = sb + (unsigned)(((0  * 2 + pp0) * QQ + c0i) * 16);
    const unsigned d1 = sb + (unsigned)(((ai1 * 2 + pp1) * QQ + c1i) * 16);
    const unsigned d2 = sb + (unsigned)(((1  * 2 + pp2) * QQ + c2i) * 16);

    // prologue: prefetch stages 0..2 into buffers 0..2
    #pragma unroll
    for (int s = 0; s < 3; s++) {
        unsigned off = s * CHUNKB;
        cp_async16(d0 + off, src0);
        cp_async16(d1 + off, src1);
        if (has2) cp_async16(d2 + off, src2);
        asm volatile("cp.async.commit_group;");
        src0 += APS * QQ; src1 += APS * QQ; src2 += APS * QQ;
    }

    float acc[8][2];
    #pragma unroll
    for (int v = 0; v < 8; v++) { acc[v][0] = 0.0f; acc[v][1] = 0.0f; }

    int cur = 0;
    for (int stg = 0; stg < STAGES; stg++) {
        asm volatile("cp.async.wait_group 2;");
        __syncthreads();

        const int a0 = 2 * stg;
        const uint4* qs = qb[cur];

        if (a0 + 1 < NA) {
            // ---- dual-angle stage (142 of 143) ----
            const float2 csA = csn[a0];
            const float2 csB = csn[a0 + 1];
            const float kfA = fmaf(csA.x, Xi, fmaf(csA.y, Yj, 91.0f));
            const float kfB = fmaf(csB.x, Xi, fmaf(csB.y, Yj, 91.0f));
            const float dkA = csA.x * 0.3125f;
            const float dkB = csB.x * 0.3125f;

            #pragma unroll
            for (int ii = 0; ii < 2; ii++) {
                float ka = fmaf((float)ii, dkA, kfA);
                float kb = fmaf((float)ii, dkB, kfB);
                int k0a = (int)ka;                  // in [0.2, 181.8]
                int k0b = (int)kb;
                float wa = ka - (float)k0a;
                float wb = kb - (float)k0b;
                __half2 w2a = __floats2half2_rn(wa, wa);
                __half2 w2b = __floats2half2_rn(wb, wb);
                #pragma unroll
                for (int gq = 0; gq < 2; gq++) {
                    uint4 qA = qs[gq * QQ + k0a];            // angle a0
                    uint4 qB = qs[2 * QQ + gq * QQ + k0b];   // angle a0+1
                    __half2 lo = __hadd2(
                        __hfma2(w2a, *(const __half2*)&qA.z, *(const __half2*)&qA.x),
                        __hfma2(w2b, *(const __half2*)&qB.z, *(const __half2*)&qB.x));
                    __half2 hi = __hadd2(
                        __hfma2(w2a, *(const __half2*)&qA.w, *(const __half2*)&qA.y),
                        __hfma2(w2b, *(const __half2*)&qB.w, *(const __half2*)&qB.y));
                    acc[gq * 4 + 0][ii] += __low2float(lo);
                    acc[gq * 4 + 1][ii] += __high2float(lo);
                    acc[gq * 4 + 2][ii] += __low2float(hi);
                    acc[gq * 4 + 3][ii] += __high2float(hi);
                }
            }
        } else {
            // ---- single-angle tail (stage 142: angle 284) ----
            const float2 csA = csn[a0];
            const float kfA = fmaf(csA.x, Xi, fmaf(csA.y, Yj, 91.0f));
            const float dkA = csA.x * 0.3125f;
            #pragma unroll
            for (int ii = 0; ii < 2; ii++) {
                float ka = fmaf((float)ii, dkA, kfA);
                int k0a = (int)ka;
                float wa = ka - (float)k0a;
                __half2 w2a = __floats2half2_rn(wa, wa);
                #pragma unroll
                for (int gq = 0; gq < 2; gq++) {
                    uint4 qA = qs[gq * QQ + k0a];
                    __half2 lo = __hfma2(w2a, *(const __half2*)&qA.z,
                                         *(const __half2*)&qA.x);
                    __half2 hi = __hfma2(w2a, *(const __half2*)&qA.w,
                                         *(const __half2*)&qA.y);
                    acc[gq * 4 + 0][ii] += __low2float(lo);
                    acc[gq * 4 + 1][ii] += __high2float(lo);
                    acc[gq * 4 + 2][ii] += __low2float(hi);
                    acc[gq * 4 + 3][ii] += __high2float(hi);
                }
            }
        }

        __syncthreads();   // all warps done reading qb[cur]

        // prefetch stage stg+3 into the freed buffer; always commit
        const int stp = stg + 3;
        if (stp < STAGES) {
            const unsigned off = cur * CHUNKB;
            const bool full = (2 * stp + 1 < NA);
            cp_async16(d0 + off, src0);
            if (full || ai1 == 0) cp_async16(d1 + off, src1);
            if (has2 && full)     cp_async16(d2 + off, src2);
            src0 += APS * QQ; src1 += APS * QQ; src2 += APS * QQ;
        }
        asm volatile("cp.async.commit_group;");

        cur = (cur == 2) ? 0 : cur + 1;
    }

    const float sc = (float)(PI_D / (double)NA);
    #pragma unroll
    for (int gq = 0; gq < 2; gq++) {
        #pragma unroll
        for (int rr = 0; rr < 4; rr++) {
            int img = bg * 8 + gq * 4 + rr;
            #pragma unroll
            for (int ii = 0; ii < 2; ii++) {
                out[(size_t)img * (NI * NI) + (size_t)(i0 + ii) * NI + j] =
                    acc[gq * 4 + rr][ii] * sc;
            }
        }
    }
}

// ================= launch =================
extern "C" void kernel_launch(void* const* d_in, const int* in_sizes, int n_in,
                              void* d_out, int out_size) {
    (void)in_sizes; (void)n_in; (void)out_size;
    const float* x = (const float*)d_in[0];
    float* out = (float*)d_out;

    uint4* qptr = nullptr;
    cudaGetSymbolAddress((void**)&qptr, g_q);

    filter_kernel<<<dim3((NA + 3) / 4, NB / 4), 192>>>(x, qptr);
    backproj_kernel<<<dim3(32, 32), 256>>>(qptr, out);
}

// round 17
// speedup vs baseline: 1.3619x; 1.0207x over previous
#include <cuda_runtime.h>
#include <cuda_fp16.h>
#include <math.h>

// ---------------- problem constants ----------------
constexpr int NB = 256;    // batch
constexpr int NA = 285;    // angles
constexpr int ND = 183;    // detectors
constexpr int NI = 128;    // image N
constexpr int QQ = 184;    // quads per row (stride)

constexpr double RHO_D    = 1.4142135623730951 * 20.0;
constexpr double DC_D     = 2.0 * RHO_D / 183.0;
constexpr double INVDC_D  = 1.0 / DC_D;
constexpr double H0_D     = 1.0 / (4.0 * DC_D * DC_D);
constexpr double SCALEQ_D = 12.0 * DC_D;
constexpr double PI_D     = 3.141592653589793;
constexpr float  DC_F     = (float)DC_D;

// filtered sinogram, fp16 4-image-interleaved (g0, delta) quads:
// Q[group][a][k] = halfs (g_b0[k],..,g_b3[k], (g[k+1]-g[k])_b0,..,_b3) (16B)
__device__ uint4 g_q[(size_t)(NB / 4) * NA * QQ];

// ================= Stage 1: ramp filter via packed f32x2 FMA ============
// Unified coefficient table GR[I] = (lo=Gs[I+1], hi=Gs[I]):
//   step s_a=2p :  PA[e] += xa * GR[2c+e]      (e = 0..7)
//   step s_b=2p+1: PA[e] += xb * GR[2c+e-1]
// -> one 9-entry sliding window per p: 1 LDS.64 + 4 LDS.128 coefficients
//    + 1 LDS.128 x + 16 FFMA2. FMA order identical to the verified scalar
//    sequence -> bitwise-equal results.
constexpr int XSTR = 204;

__device__ __forceinline__ void ffma2(unsigned long long& acc,
                                      unsigned long long a,
                                      unsigned long long b) {
    asm("fma.rn.f32x2 %0, %1, %2, %0;" : "+l"(acc) : "l"(a), "l"(b));
}

__global__ __launch_bounds__(192) void filter_kernel(const float* __restrict__ x,
                                                     uint4* __restrict__ Q) {
    // xs rows: stride XSTR floats, rows >=8 offset +16 floats
    __shared__ __align__(16) float  xs[16 * XSTR + 16];
    __shared__ __align__(16) float  Gs[224];          // Godd shifted +8, guarded
    __shared__ __align__(16) float2 GR[224];          // GR[I] = (Gs[I+1], Gs[I])
    __shared__ __align__(16) __half st[4 * 184 * 4];  // [va][n][im]

    const int t  = threadIdx.x;
    const int a0 = blockIdx.x * 4;                  // angle quad
    const int g  = blockIdx.y;                      // image group
    const int b0 = 4 * g;

    // Gs[j] = g(2*(j-8)-181) for j-8 in [0,181], else 0
    for (int jj = t; jj < 224; jj += 192) {
        int i = jj - 8;
        float v = 0.0f;
        if (i >= 0 && i <= 181) {
            int o = 2 * i - 181;                    // odd
            float d = 3.14159265358979f * (float)o * DC_F;
            v = -1.0f / (d * d);
        }
        Gs[jj] = v;
    }

    // load 16 rows (row = va*4 + im), zero-padded to XSTR, swizzled base
    for (int u = t; u < 16 * XSTR; u += 192) {
        int row = u / XSTR, col = u - row * XSTR;
        int va = row >> 2, im = row & 3;
        int aa = a0 + va;
        float v = 0.0f;
        if (col < ND && aa < NA)
            v = x[((size_t)(b0 + im) * NA + aa) * ND + col];
        xs[row * XSTR + ((row & 8) << 1) + col] = v;
    }
    __syncthreads();

    for (int i = t; i < 224; i += 192) {
        float lo = (i + 1 < 224) ? Gs[i + 1] : 0.0f;
        GR[i] = make_float2(lo, Gs[i]);
    }
    __syncthreads();

    const int r  = t & 15;           // row 0..15
    const int l  = t >> 4;           // 0..11
    const int va = r >> 2, im = r & 3;
    const int n0 = 16 * l;
    const int C0 = 4 * l + 49;
    const float* xr = xs + r * XSTR + ((r & 8) << 1);

    unsigned long long PA[8];
    #pragma unroll
    for (int e = 0; e < 8; e++) PA[e] = 0ULL;

    const unsigned long long* GRu = (const unsigned long long*)GR;
    const ulonglong2*         GR4 = (const ulonglong2*)GR;

    // 48 pairs cover s = 0..95 (s=92..95 multiply padded zeros -> exact 0)
    #pragma unroll 4
    for (int p = 0; p < 48; p++) {
        const int c = C0 - p;                       // c in [2, 93]
        ulonglong2 xp = *(const ulonglong2*)(xr + 4 * p);   // LDS.128
        unsigned long long xa = xp.x, xb = xp.y;
        // coefficient window GRu[2c-1 .. 2c+7]; g[off] = GRu[2c-2+off]
        unsigned long long g1 = GRu[2 * c - 1];             // LDS.64
        ulonglong2 W1 = GR4[c],     W2 = GR4[c + 1];        // LDS.128 x4
        ulonglong2 W3 = GR4[c + 2], W4 = GR4[c + 3];
        unsigned long long gw[10];
        gw[1] = g1;
        gw[2] = W1.x; gw[3] = W1.y;
        gw[4] = W2.x; gw[5] = W2.y;
        gw[6] = W3.x; gw[7] = W3.y;
        gw[8] = W4.x; gw[9] = W4.y;
        #pragma unroll
        for (int e = 0; e < 8; e++) ffma2(PA[e], xa, gw[e + 2]);  // s_a = 2p
        #pragma unroll
        for (int e = 0; e < 8; e++) ffma2(PA[e], xb, gw[e + 1]);  // s_b = 2p+1
    }

    // unpack: PA[e] = (lo = acc[2e+1], hi = acc[2e])
    float acc[16];
    #pragma unroll
    for (int e = 0; e < 8; e++) {
        float lo, hi;
        asm("mov.b64 {%0, %1}, %2;" : "=f"(lo), "=f"(hi) : "l"(PA[e]));
        acc[2 * e]     = hi;
        acc[2 * e + 1] = lo;
    }

    { // center tap
        const float h0 = (float)H0_D;
        float4 c0 = *(const float4*)(xr + n0);
        float4 c1 = *(const float4*)(xr + n0 + 4);
        float4 c2 = *(const float4*)(xr + n0 + 8);
        float4 c3 = *(const float4*)(xr + n0 + 12);
        float cf[16] = {c0.x,c0.y,c0.z,c0.w, c1.x,c1.y,c1.z,c1.w,
                        c2.x,c2.y,c2.z,c2.w, c3.x,c3.y,c3.z,c3.w};
        #pragma unroll
        for (int e = 0; e < 16; e++) acc[e] = fmaf(h0, cf[e], acc[e]);
    }

    // stage as fp16: st[(va*184 + n)*4 + im]
    const float sc = (float)SCALEQ_D;
    #pragma unroll
    for (int e = 0; e < 16; e++) {
        int n = n0 + e;
        if (n < 184) st[(va * 184 + n) * 4 + im] = __float2half_rn(acc[e] * sc);
    }
    __syncthreads();

    // pack (g0, delta) quads
    for (int u = t; u < 4 * ND; u += 192) {
        int qa = u / ND, k = u - qa * ND;
        int aa = a0 + qa;
        if (aa < NA) {
            const uint2* sp = (const uint2*)(st + qa * 184 * 4);
            uint2 lo = sp[k];
            uint2 hi = sp[k + 1];
            __half2 dd0 = __hsub2(*(const __half2*)&hi.x, *(const __half2*)&lo.x);
            __half2 dd1 = __hsub2(*(const __half2*)&hi.y, *(const __half2*)&lo.y);
            Q[((size_t)g * NA + aa) * QQ + k] =
                make_uint4(lo.x, lo.y, *(const unsigned*)&dd0, *(const unsigned*)&dd1);
        }
    }
}

// ================= Stage 2: backprojection =================
// R15 config; flush now uses packed add.rn.f32x2 (2 CVT + 1 FADD2 per
// half2 instead of 2 CVT + 2 FADD). Same f32 adds per lane, same order
// -> bitwise-identical results.
constexpr int APS    = 2;
constexpr int STAGES = (NA + APS - 1) / APS;   // 143
constexpr int CHUNK  = APS * 2 * QQ;           // 736
constexpr unsigned CHUNKB = CHUNK * 16;

__device__ __forceinline__ void cp_async16(unsigned dst, const void* src) {
    asm volatile("cp.async.cg.shared.global [%0], [%1], 16;" :: "r"(dst), "l"(src));
}

// accp += (f32(v.lo), f32(v.hi)) as one packed f32x2 add
__device__ __forceinline__ void acc2(unsigned long long& accp, unsigned v) {
    asm("{\n\t"
        ".reg .b16 l, h;\n\t"
        ".reg .f32 fl, fh;\n\t"
        ".reg .b64 p;\n\t"
        "mov.b32 {l, h}, %1;\n\t"
        "cvt.f32.f16 fl, l;\n\t"
        "cvt.f32.f16 fh, h;\n\t"
        "mov.b64 p, {fl, fh};\n\t"
        "add.rn.f32x2 %0, %0, p;\n\t"
        "}" : "+l"(accp) : "r"(v));
}

__global__ __launch_bounds__(256, 5) void backproj_kernel(const uint4* __restrict__ Q,
                                                          float* __restrict__ out) {
    __shared__ uint4  qb[3][CHUNK];    // 35328 B
    __shared__ float2 csn[NA];         //  2280 B -> 37.6 KB total

    const int t   = threadIdx.x;
    const int seg = blockIdx.x;        // 0..31 -> image rows [seg*4, seg*4+4)
    const int bg  = blockIdx.y;        // 0..31 -> images [bg*8, bg*8+8)

    for (int idx = t; idx < NA; idx += 256) {
        float th = ((float)idx + 0.5f) * (float)(PI_D / (double)NA);
        float s, c;
        sincosf(th, &s, &c);
        csn[idx] = make_float2(c * (float)INVDC_D, s * (float)INVDC_D);
    }

    const int j  = t & 127;
    const int i0 = seg * 4 + (t >> 7) * 2;
    const float Yj = -20.0f + ((float)j  + 0.5f) * 0.3125f;
    const float Xi = -20.0f + ((float)i0 + 0.5f) * 0.3125f;

    const uint4* Qb = Q + (size_t)(bg * 2) * NA * QQ;

    // hoisted 3-slot chunk decomposition over [0, 736)
    const int pp0 = t / 184,               c0i = t - pp0 * 184;
    const int u1  = t + 256;
    const int ai1 = (u1 >= 368) ? 1 : 0;
    const int v1  = u1 - ai1 * 368;
    const int pp1 = v1 / 184,              c1i = v1 - pp1 * 184;
    const int u2  = t + 512;
    const bool has2 = (u2 < CHUNK);
    const int v2  = u2 - 368;
    const int pp2 = has2 ? (v2 / 184) : 0, c2i = has2 ? (v2 - (v2 / 184) * 184) : 0;

    const uint4* src0 = Qb + ((size_t)pp0 * NA + 0  ) * QQ + c0i;
    const uint4* src1 = Qb + ((size_t)pp1 * NA + ai1) * QQ + c1i;
    const uint4* src2 = Qb + ((size_t)pp2 * NA + 1  ) * QQ + c2i;

    const unsigned sb = (unsigned)__cvta_generic_to_shared(&qb[0][0]);
    const unsigned d0 = sb + (unsigned)(((0  * 2 + pp0) * QQ + c0i) * 16);
    const unsigned d1 = sb + (unsigned)(((ai1 * 2 + pp1) * QQ + c1i) * 16);
    const unsigned d2 = sb + (unsigned)(((1  * 2 + pp2) * QQ + c2i) * 16);

    // prologue: prefetch stages 0..2 into buffers 0..2
    #pragma unroll
    for (int s = 0; s < 3; s++) {
        unsigned off = s * CHUNKB;
        cp_async16(d0 + off, src0);
        cp_async16(d1 + off, src1);
        if (has2) cp_async16(d2 + off, src2);
        asm volatile("cp.async.commit_group;");
        src0 += APS * QQ; src1 += APS * QQ; src2 += APS * QQ;
    }

    // packed accumulators: accp[gq*2+h][ii] = (acc_b(2h), acc_b(2h+1))
    unsigned long long accp[4][2];
    #pragma unroll
    for (int v = 0; v < 4; v++) { accp[v][0] = 0ULL; accp[v][1] = 0ULL; }

    int cur = 0;
    for (int stg = 0; stg < STAGES; stg++) {
        asm volatile("cp.async.wait_group 2;");
        __syncthreads();

        const int a0 = 2 * stg;
        const uint4* qs = qb[cur];

        if (a0 + 1 < NA) {
            // ---- dual-angle stage (142 of 143) ----
            const float2 csA = csn[a0];
            const float2 csB = csn[a0 + 1];
            const float kfA = fmaf(csA.x, Xi, fmaf(csA.y, Yj, 91.0f));
            const float kfB = fmaf(csB.x, Xi, fmaf(csB.y, Yj, 91.0f));
            const float dkA = csA.x * 0.3125f;
            const float dkB = csB.x * 0.3125f;

            #pragma unroll
            for (int ii = 0; ii < 2; ii++) {
                float ka = fmaf((float)ii, dkA, kfA);
                float kb = fmaf((float)ii, dkB, kfB);
                int k0a = (int)ka;                  // in [0.2, 181.8]
                int k0b = (int)kb;
                float wa = ka - (float)k0a;
                float wb = kb - (float)k0b;
                __half2 w2a = __floats2half2_rn(wa, wa);
                __half2 w2b = __floats2half2_rn(wb, wb);
                #pragma unroll
                for (int gq = 0; gq < 2; gq++) {
                    uint4 qA = qs[gq * QQ + k0a];            // angle a0
                    uint4 qB = qs[2 * QQ + gq * QQ + k0b];   // angle a0+1
                    __half2 lo = __hadd2(
                        __hfma2(w2a, *(const __half2*)&qA.z, *(const __half2*)&qA.x),
                        __hfma2(w2b, *(const __half2*)&qB.z, *(const __half2*)&qB.x));
                    __half2 hi = __hadd2(
                        __hfma2(w2a, *(const __half2*)&qA.w, *(const __half2*)&qA.y),
                        __hfma2(w2b, *(const __half2*)&qB.w, *(const __half2*)&qB.y));
                    acc2(accp[gq * 2 + 0][ii], *(const unsigned*)&lo);
                    acc2(accp[gq * 2 + 1][ii], *(const unsigned*)&hi);
                }
            }
        } else {
            // ---- single-angle tail (stage 142: angle 284) ----
            const float2 csA = csn[a0];
            const float kfA = fmaf(csA.x, Xi, fmaf(csA.y, Yj, 91.0f));
            const float dkA = csA.x * 0.3125f;
            #pragma unroll
            for (int ii = 0; ii < 2; ii++) {
                float ka = fmaf((float)ii, dkA, kfA);
                int k0a = (int)ka;
                float wa = ka - (float)k0a;
                __half2 w2a = __floats2half2_rn(wa, wa);
                #pragma unroll
                for (int gq = 0; gq < 2; gq++) {
                    uint4 qA = qs[gq * QQ + k0a];
                    __half2 lo = __hfma2(w2a, *(const __half2*)&qA.z,
                                         *(const __half2*)&qA.x);
                    __half2 hi = __hfma2(w2a, *(const __half2*)&qA.w,
                                         *(const __half2*)&qA.y);
                    acc2(accp[gq * 2 + 0][ii], *(const unsigned*)&lo);
                    acc2(accp[gq * 2 + 1][ii], *(const unsigned*)&hi);
                }
            }
        }

        __syncthreads();   // all warps done reading qb[cur]

        // prefetch stage stg+3 into the freed buffer; always commit
        const int stp = stg + 3;
        if (stp < STAGES) {
            const unsigned off = cur * CHUNKB;
            const bool full = (2 * stp + 1 < NA);
            cp_async16(d0 + off, src0);
            if (full || ai1 == 0) cp_async16(d1 + off, src1);
            if (has2 && full)     cp_async16(d2 + off, src2);
            src0 += APS * QQ; src1 += APS * QQ; src2 += APS * QQ;
        }
        asm volatile("cp.async.commit_group;");

        cur = (cur == 2) ? 0 : cur + 1;
    }

    const float sc = (float)(PI_D / (double)NA);
    #pragma unroll
    for (int gq = 0; gq < 2; gq++) {
        #pragma unroll
        for (int h = 0; h < 2; h++) {
            #pragma unroll
            for (int ii = 0; ii < 2; ii++) {
                float f0, f1;
                asm("mov.b64 {%0, %1}, %2;"
                    : "=f"(f0), "=f"(f1) : "l"(accp[gq * 2 + h][ii]));
                int img0 = bg * 8 + gq * 4 + 2 * h;
                out[(size_t)img0 * (NI * NI) + (size_t)(i0 + ii) * NI + j] = f0 * sc;
                out[(size_t)(img0 + 1) * (NI * NI) + (size_t)(i0 + ii) * NI + j] = f1 * sc;
            }
        }
    }
}

// ================= launch =================
extern "C" void kernel_launch(void* const* d_in, const int* in_sizes, int n_in,
                              void* d_out, int out_size) {
    (void)in_sizes; (void)n_in; (void)out_size;
    const float* x = (const float*)d_in[0];
    float* out = (float*)d_out;

    uint4* qptr = nullptr;
    cudaGetSymbolAddress((void**)&qptr, g_q);

    filter_kernel<<<dim3((NA + 3) / 4, NB / 4), 192>>>(x, qptr);
    backproj_kernel<<<dim3(32, 32), 256>>>(qptr, out);
}